// round 13
// baseline (speedup 1.0000x reference)
#include <cuda_runtime.h>
#include <cuda_fp16.h>
#include <cstdint>

#define M_TOTAL 16384
#define N_TOTAL 4096
#define K_TOTAL 4096
#define NSLOT   8

#define BM 128
#define BN 256
#define BK 128                 // halves per k-tile: 256B per row
#define STAGES 2
#define ROWB 256               // bytes per smem row (no pad; XOR swizzle)
#define KT (K_TOTAL / BK)      // 32
#define A_STAGE (BM * ROWB)    // 32768
#define B_STAGE (BN * ROWB)    // 65536

// Scratch (allocation-free rule: __device__ globals)
__device__ __half g_W[(size_t)N_TOTAL * K_TOTAL];
__device__ __half g_X[(size_t)M_TOTAL * K_TOTAL];
__device__ float  g_b[N_TOTAL];

// ---------------------------------------------------------------------------
// Kernel 1: W = fp16(weight + sum_i (scale_i*wscale_i)*wq_i + (scale . wzp))
// ---------------------------------------------------------------------------
__global__ void compute_w_kernel(const float* __restrict__ weight,
                                 const int*   __restrict__ wq,
                                 const float* __restrict__ scale,
                                 const float* __restrict__ wscale,
                                 const int*   __restrict__ wzp) {
    const size_t nvec = (size_t)N_TOTAL * K_TOTAL / 4;
    size_t idx = (size_t)blockIdx.x * blockDim.x + threadIdx.x;
    if (idx >= nvec) return;

    float c[NSLOT];
    float z = 0.f;
#pragma unroll
    for (int i = 0; i < NSLOT; i++) {
        float s = scale[i];
        c[i] = s * wscale[i];
        z += s * (float)wzp[i];
    }
    float4 w = reinterpret_cast<const float4*>(weight)[idx];
    float ax = w.x + z, ay = w.y + z, az = w.z + z, aw = w.w + z;
#pragma unroll
    for (int i = 0; i < NSLOT; i++) {
        int4 q = reinterpret_cast<const int4*>(wq)[(size_t)i * nvec + idx];
        ax += c[i] * (float)q.x;
        ay += c[i] * (float)q.y;
        az += c[i] * (float)q.z;
        aw += c[i] * (float)q.w;
    }
    __half2 lo = __floats2half2_rn(ax, ay);
    __half2 hi = __floats2half2_rn(az, aw);
    reinterpret_cast<uint2*>(g_W)[idx] =
        make_uint2(*reinterpret_cast<uint32_t*>(&lo), *reinterpret_cast<uint32_t*>(&hi));
}

// ---------------------------------------------------------------------------
// Kernel 1b: X -> fp16
// ---------------------------------------------------------------------------
__global__ void round_x_kernel(const float* __restrict__ x) {
    const size_t nvec = (size_t)M_TOTAL * K_TOTAL / 4;
    size_t idx = (size_t)blockIdx.x * blockDim.x + threadIdx.x;
    if (idx >= nvec) return;
    float4 v = reinterpret_cast<const float4*>(x)[idx];
    __half2 lo = __floats2half2_rn(v.x, v.y);
    __half2 hi = __floats2half2_rn(v.z, v.w);
    reinterpret_cast<uint2*>(g_X)[idx] =
        make_uint2(*reinterpret_cast<uint32_t*>(&lo), *reinterpret_cast<uint32_t*>(&hi));
}

// ---------------------------------------------------------------------------
// Kernel 2: b = bias + sum_i scale_i*(bscale_i*bq_i + bzp_i)
// ---------------------------------------------------------------------------
__global__ void compute_b_kernel(const float* __restrict__ bias,
                                 const float* __restrict__ scale,
                                 const int*   __restrict__ bq,
                                 const float* __restrict__ bscale,
                                 const int*   __restrict__ bzp) {
    int j = blockIdx.x * blockDim.x + threadIdx.x;
    if (j >= N_TOTAL) return;
    float acc = bias[j];
#pragma unroll
    for (int i = 0; i < NSLOT; i++)
        acc += scale[i] * (bscale[i] * (float)bq[i * N_TOTAL + j] + (float)bzp[i]);
    g_b[j] = acc;
}

// ---------------------------------------------------------------------------
// Kernel 3: fp16 m16n8k16 GEMM, fp32 acc. CTA 128x256x128, 8 warps (2x4),
// warp tile 64x64, STAGES=2, XOR-swizzled 256B rows, 32 k-tiles (4x fewer
// barriers), frag double-buffer over 8 ks-steps. 1 CTA/SM.
// ---------------------------------------------------------------------------
extern __shared__ __half smem_h[];

__global__ void __launch_bounds__(256, 1)
gemm_fp16_kernel(float* __restrict__ OUT) {
    const int tid  = threadIdx.x;
    const int warp = tid >> 5;
    const int lane = tid & 31;
    const int wm = warp >> 2;   // 0..1 : 64 rows
    const int wn = warp & 3;    // 0..3 : 64 cols
    const int bm = blockIdx.y * BM;
    const int bn = blockIdx.x * BN;

    const uint32_t S_u  = (uint32_t)__cvta_generic_to_shared(smem_h);
    const uint32_t As_u = S_u;                       // 2 * A_STAGE
    const uint32_t Bs_u = S_u + STAGES * A_STAGE;    // 2 * B_STAGE

    // ---- producer: 96KB per tile, 24 cp.async per thread, XOR swizzle ----
    // A: thread t -> row (t&127), chunks (t>>7)*8 .. +7
    // B: thread t -> row t, chunks 0..15
    const int arow = tid & 127;
    const int acb  = (tid >> 7) * 8;
    const __half* a_src0 = g_X + (size_t)(bm + arow) * K_TOTAL + acb * 8;
    const __half* b_src0 = g_W + (size_t)(bn + tid) * K_TOTAL;
    const uint32_t a_dst0 = As_u + arow * ROWB;
    const uint32_t b_dst0 = Bs_u + tid * ROWB;
    const int amask = arow & 7;
    const int bmask = tid & 7;

    auto issue_tile = [&](int t) {
        const int s = t & 1;
        const int kofs = t * BK;
        {
            uint32_t dst = a_dst0 + s * A_STAGE;
            const __half* src = a_src0 + kofs;
#pragma unroll
            for (int j = 0; j < 8; j++) {
                uint32_t sw = (uint32_t)(((acb + j) ^ amask) << 4);
                asm volatile("cp.async.cg.shared.global [%0], [%1], 16;\n"
                             :: "r"(dst + sw), "l"(src + j * 8));
            }
        }
        {
            uint32_t dst = b_dst0 + s * B_STAGE;
            const __half* src = b_src0 + kofs;
#pragma unroll
            for (int j = 0; j < 16; j++) {
                uint32_t sw = (uint32_t)((j ^ bmask) << 4);
                asm volatile("cp.async.cg.shared.global [%0], [%1], 16;\n"
                             :: "r"(dst + sw), "l"(src + j * 8));
            }
        }
    };

    float acc[4][8][4];
#pragma unroll
    for (int mt = 0; mt < 4; mt++)
#pragma unroll
        for (int nt = 0; nt < 8; nt++)
#pragma unroll
            for (int r = 0; r < 4; r++) acc[mt][nt][r] = 0.f;

    // ---- consumer lane addressing (XOR swizzle) ----
    const int rowA  = wm * 64 + (lane & 15);
    const int hiA   = lane >> 4;              // 16B chunk parity within ks
    const int maskA = rowA & 7;
    const int rowB  = wn * 64 + ((lane >> 4) * 8 + (lane & 7));
    const int hiB   = (lane >> 3) & 1;
    const int maskB = rowB & 7;
    const uint32_t aRow_u = As_u + rowA * ROWB;   // + mt*16*ROWB + stage
    const uint32_t bRow_u = Bs_u + rowB * ROWB;   // + pr*16*ROWB + stage

    const int q = lane >> 2;
    const int c = lane & 3;

    uint32_t afr[2][4][4];
    uint32_t bfr[2][8][2];

    issue_tile(0);
    asm volatile("cp.async.commit_group;\n");

    for (int t = 0; t < KT; t++) {
        if (t + 1 < KT) {
            issue_tile(t + 1);                        // fills stage (t+1)&1
            asm volatile("cp.async.commit_group;\n");
            asm volatile("cp.async.wait_group 1;\n"); // tile t arrived
        } else {
            asm volatile("cp.async.wait_group 0;\n");
        }
        __syncthreads();   // tile t visible to all warps

        const int s = t & 1;
        const uint32_t aB = aRow_u + s * A_STAGE;
        const uint32_t bB = bRow_u + s * B_STAGE;

        auto loadA = [&](int ks, int buf) {
            const uint32_t off = (uint32_t)(((ks * 2 + hiA) ^ maskA) << 4);
#pragma unroll
            for (int mt = 0; mt < 4; mt++) {
                asm volatile(
                    "ldmatrix.sync.aligned.m8n8.x4.shared.b16 {%0,%1,%2,%3}, [%4];"
                    : "=r"(afr[buf][mt][0]), "=r"(afr[buf][mt][1]),
                      "=r"(afr[buf][mt][2]), "=r"(afr[buf][mt][3])
                    : "r"(aB + mt * 16 * ROWB + off));
            }
        };
        auto loadB = [&](int ks, int buf) {
            const uint32_t off = (uint32_t)(((ks * 2 + hiB) ^ maskB) << 4);
#pragma unroll
            for (int pr = 0; pr < 4; pr++) {
                asm volatile(
                    "ldmatrix.sync.aligned.m8n8.x4.shared.b16 {%0,%1,%2,%3}, [%4];"
                    : "=r"(bfr[buf][2 * pr][0]), "=r"(bfr[buf][2 * pr][1]),
                      "=r"(bfr[buf][2 * pr + 1][0]), "=r"(bfr[buf][2 * pr + 1][1])
                    : "r"(bB + pr * 16 * ROWB + off));
            }
        };
        auto mma_step = [&](int buf) {
#pragma unroll
            for (int mt = 0; mt < 4; mt++) {
#pragma unroll
                for (int nt = 0; nt < 8; nt++) {
                    asm volatile(
                        "mma.sync.aligned.m16n8k16.row.col.f32.f16.f16.f32 "
                        "{%0,%1,%2,%3}, {%4,%5,%6,%7}, {%8,%9}, {%0,%1,%2,%3};\n"
                        : "+f"(acc[mt][nt][0]), "+f"(acc[mt][nt][1]),
                          "+f"(acc[mt][nt][2]), "+f"(acc[mt][nt][3])
                        : "r"(afr[buf][mt][0]), "r"(afr[buf][mt][1]),
                          "r"(afr[buf][mt][2]), "r"(afr[buf][mt][3]),
                          "r"(bfr[buf][nt][0]), "r"(bfr[buf][nt][1]));
                }
            }
        };

        loadA(0, 0);
        loadB(0, 0);
#pragma unroll
        for (int ks = 0; ks < 8; ks++) {
            if (ks < 7) {
                loadA(ks + 1, (ks + 1) & 1);
                loadB(ks + 1, (ks + 1) & 1);
            }
            mma_step(ks & 1);
        }
        __syncthreads();   // all warps done reading stage t&1
    }

    // epilogue: bias + store (C fragment layout of m16n8)
#pragma unroll
    for (int mt = 0; mt < 4; mt++) {
        const int row0 = bm + wm * 64 + mt * 16 + q;
#pragma unroll
        for (int nt = 0; nt < 8; nt++) {
            const int col = bn + wn * 64 + nt * 8 + c * 2;
            const float b0 = g_b[col];
            const float b1 = g_b[col + 1];
            float2 v0 = make_float2(acc[mt][nt][0] + b0, acc[mt][nt][1] + b1);
            float2 v1 = make_float2(acc[mt][nt][2] + b0, acc[mt][nt][3] + b1);
            *reinterpret_cast<float2*>(OUT + (size_t)row0 * N_TOTAL + col) = v0;
            *reinterpret_cast<float2*>(OUT + (size_t)(row0 + 8) * N_TOTAL + col) = v1;
        }
    }
}

// ---------------------------------------------------------------------------
extern "C" void kernel_launch(void* const* d_in, const int* in_sizes, int n_in,
                              void* d_out, int out_size) {
    const float* x      = (const float*)d_in[0];
    const float* weight = (const float*)d_in[1];
    const float* bias   = (const float*)d_in[2];
    const float* scale  = (const float*)d_in[3];
    const int*   wq     = (const int*)  d_in[4];
    const float* wscale = (const float*)d_in[5];
    const int*   wzp    = (const int*)  d_in[6];
    const int*   bq     = (const int*)  d_in[7];
    const float* bscale = (const float*)d_in[8];
    const int*   bzp    = (const int*)  d_in[9];
    float* out = (float*)d_out;

    {
        const size_t nvec = (size_t)N_TOTAL * K_TOTAL / 4;
        compute_w_kernel<<<(int)((nvec + 255) / 256), 256>>>(weight, wq, scale, wscale, wzp);
    }
    {
        const size_t nvec = (size_t)M_TOTAL * K_TOTAL / 4;
        round_x_kernel<<<(int)((nvec + 255) / 256), 256>>>(x);
    }
    compute_b_kernel<<<(N_TOTAL + 255) / 256, 256>>>(bias, scale, bq, bscale, bzp);

    {
        int smem_bytes = STAGES * (A_STAGE + B_STAGE);   // 196608
        cudaFuncSetAttribute(gemm_fp16_kernel,
                             cudaFuncAttributeMaxDynamicSharedMemorySize, smem_bytes);
        dim3 grid(N_TOTAL / BN, M_TOTAL / BM);   // (16, 128)
        gemm_fp16_kernel<<<grid, 256, smem_bytes>>>(out);
    }
}

// round 14
// speedup vs baseline: 1.5831x; 1.5831x over previous
#include <cuda_runtime.h>
#include <cuda_fp16.h>
#include <cstdint>

#define M_TOTAL 16384
#define N_TOTAL 4096
#define K_TOTAL 4096
#define NSLOT   8

#define BM 128
#define BN 64
#define BK 64
#define STAGES 2
#define PADH 8
#define TSH (BK + PADH)        // 72 halves per row
#define ROWB (TSH * 2)         // 144 bytes per row
#define KT (K_TOTAL / BK)      // 64
#define ROWS_TOT (BM + BN)     // 192 rows per stage (A then B)
#define STAGE_B (ROWS_TOT * ROWB)  // 27648 bytes

// Scratch (allocation-free rule: __device__ globals)
__device__ __half g_W[(size_t)N_TOTAL * K_TOTAL];
__device__ __half g_X[(size_t)M_TOTAL * K_TOTAL];
__device__ float  g_b[N_TOTAL];

// ---------------------------------------------------------------------------
// Kernel 1: W = fp16(weight + sum_i (scale_i*wscale_i)*wq_i + (scale . wzp))
// ---------------------------------------------------------------------------
__global__ void compute_w_kernel(const float* __restrict__ weight,
                                 const int*   __restrict__ wq,
                                 const float* __restrict__ scale,
                                 const float* __restrict__ wscale,
                                 const int*   __restrict__ wzp) {
    const size_t nvec = (size_t)N_TOTAL * K_TOTAL / 4;
    size_t idx = (size_t)blockIdx.x * blockDim.x + threadIdx.x;
    if (idx >= nvec) return;

    float c[NSLOT];
    float z = 0.f;
#pragma unroll
    for (int i = 0; i < NSLOT; i++) {
        float s = scale[i];
        c[i] = s * wscale[i];
        z += s * (float)wzp[i];
    }
    float4 w = reinterpret_cast<const float4*>(weight)[idx];
    float ax = w.x + z, ay = w.y + z, az = w.z + z, aw = w.w + z;
#pragma unroll
    for (int i = 0; i < NSLOT; i++) {
        int4 q = reinterpret_cast<const int4*>(wq)[(size_t)i * nvec + idx];
        ax += c[i] * (float)q.x;
        ay += c[i] * (float)q.y;
        az += c[i] * (float)q.z;
        aw += c[i] * (float)q.w;
    }
    __half2 lo = __floats2half2_rn(ax, ay);
    __half2 hi = __floats2half2_rn(az, aw);
    reinterpret_cast<uint2*>(g_W)[idx] =
        make_uint2(*reinterpret_cast<uint32_t*>(&lo), *reinterpret_cast<uint32_t*>(&hi));
}

// ---------------------------------------------------------------------------
// Kernel 1b: X -> fp16
// ---------------------------------------------------------------------------
__global__ void round_x_kernel(const float* __restrict__ x) {
    const size_t nvec = (size_t)M_TOTAL * K_TOTAL / 4;
    size_t idx = (size_t)blockIdx.x * blockDim.x + threadIdx.x;
    if (idx >= nvec) return;
    float4 v = reinterpret_cast<const float4*>(x)[idx];
    __half2 lo = __floats2half2_rn(v.x, v.y);
    __half2 hi = __floats2half2_rn(v.z, v.w);
    reinterpret_cast<uint2*>(g_X)[idx] =
        make_uint2(*reinterpret_cast<uint32_t*>(&lo), *reinterpret_cast<uint32_t*>(&hi));
}

// ---------------------------------------------------------------------------
// Kernel 2: b = bias + sum_i scale_i*(bscale_i*bq_i + bzp_i)
// ---------------------------------------------------------------------------
__global__ void compute_b_kernel(const float* __restrict__ bias,
                                 const float* __restrict__ scale,
                                 const int*   __restrict__ bq,
                                 const float* __restrict__ bscale,
                                 const int*   __restrict__ bzp) {
    int j = blockIdx.x * blockDim.x + threadIdx.x;
    if (j >= N_TOTAL) return;
    float acc = bias[j];
#pragma unroll
    for (int i = 0; i < NSLOT; i++)
        acc += scale[i] * (bscale[i] * (float)bq[i * N_TOTAL + j] + (float)bzp[i]);
    g_b[j] = acc;
}

// ---------------------------------------------------------------------------
// Kernel 3: fp16 m16n8k16 GEMM, fp32 acc. CTA 128x64x64, 8 warps (4x2),
// warp tile 32x32, 2-stage cp.async, single barrier per k-tile.
// 3 CTAs/SM => 6 warps/SMSP.
// ---------------------------------------------------------------------------
extern __shared__ __half smem_h[];

__global__ void __launch_bounds__(256, 3)
gemm_fp16_kernel(float* __restrict__ OUT) {
    const int tid  = threadIdx.x;
    const int warp = tid >> 5;
    const int lane = tid & 31;
    const int wm = warp >> 1;   // 0..3 : 32 rows
    const int wn = warp & 1;    // 0..1 : 32 cols
    const int bm = blockIdx.y * BM;
    const int bn = blockIdx.x * BN;

    const uint32_t S_u = (uint32_t)__cvta_generic_to_shared(smem_h);

    // producer mapping: chunk c = tid + 256*j (j=0..5), row = c>>3 = (tid>>3)+32j,
    // col chunk = tid&7. Rows 0..127 = A, 128..191 = B. Fixed col per thread.
    const int prow0 = tid >> 3;          // 0..31
    const int pcc   = tid & 7;           // 16B chunk index
    const __half* aP = g_X + (size_t)(bm + prow0) * K_TOTAL + pcc * 8;
    const __half* bP = g_W + (size_t)(bn + prow0) * K_TOTAL + pcc * 8;
    const uint32_t d0 = S_u + prow0 * ROWB + pcc * 16;

    auto issue_tile = [&](int t) {
        const uint32_t sb = (uint32_t)((t & 1) * STAGE_B);
        const int kofs = t * BK;
#pragma unroll
        for (int j = 0; j < 4; j++) {   // A rows prow0 + 32j
            asm volatile("cp.async.cg.shared.global [%0], [%1], 16;\n"
                         :: "r"(d0 + sb + j * 32 * ROWB),
                            "l"(aP + (size_t)j * 32 * K_TOTAL + kofs));
        }
#pragma unroll
        for (int j = 0; j < 2; j++) {   // B rows prow0 + 32j (smem rows 128+)
            asm volatile("cp.async.cg.shared.global [%0], [%1], 16;\n"
                         :: "r"(d0 + sb + (128 + j * 32) * ROWB),
                            "l"(bP + (size_t)j * 32 * K_TOTAL + kofs));
        }
    };

    float acc[2][4][4];
#pragma unroll
    for (int mt = 0; mt < 2; mt++)
#pragma unroll
        for (int nt = 0; nt < 4; nt++)
#pragma unroll
            for (int r = 0; r < 4; r++) acc[mt][nt][r] = 0.f;

    // ldmatrix per-lane base offsets (bytes within a stage)
    const uint32_t a_lm = (uint32_t)((wm * 32 + (lane & 15)) * ROWB + (lane >> 4) * 16);
    const uint32_t b_lm = (uint32_t)((128 + wn * 32 + ((lane >> 4) * 8 + (lane & 7))) * ROWB
                                     + ((lane >> 3) & 1) * 16);

    const int q = lane >> 2;
    const int c = lane & 3;

    // prologue
    issue_tile(0);
    asm volatile("cp.async.commit_group;\n");

    for (int t = 0; t < KT; t++) {
        asm volatile("cp.async.wait_group 0;\n");   // tile t arrived
        __syncthreads();                            // visible; prior reads done

        if (t + 1 < KT) {
            issue_tile(t + 1);
            asm volatile("cp.async.commit_group;\n");
        }

        const uint32_t sb = (uint32_t)((t & 1) * STAGE_B);
        const uint32_t aS = S_u + sb + a_lm;
        const uint32_t bS = S_u + sb + b_lm;

#pragma unroll
        for (int ks = 0; ks < 4; ks++) {
            const uint32_t kb = (uint32_t)ks * 32;
            uint32_t afr[2][4];
#pragma unroll
            for (int mt = 0; mt < 2; mt++) {
                asm volatile(
                    "ldmatrix.sync.aligned.m8n8.x4.shared.b16 {%0,%1,%2,%3}, [%4];"
                    : "=r"(afr[mt][0]), "=r"(afr[mt][1]),
                      "=r"(afr[mt][2]), "=r"(afr[mt][3])
                    : "r"(aS + mt * 16 * ROWB + kb));
            }
            uint32_t bfr[4][2];
#pragma unroll
            for (int pr = 0; pr < 2; pr++) {
                asm volatile(
                    "ldmatrix.sync.aligned.m8n8.x4.shared.b16 {%0,%1,%2,%3}, [%4];"
                    : "=r"(bfr[2 * pr][0]), "=r"(bfr[2 * pr][1]),
                      "=r"(bfr[2 * pr + 1][0]), "=r"(bfr[2 * pr + 1][1])
                    : "r"(bS + pr * 16 * ROWB + kb));
            }
#pragma unroll
            for (int mt = 0; mt < 2; mt++) {
#pragma unroll
                for (int nt = 0; nt < 4; nt++) {
                    asm volatile(
                        "mma.sync.aligned.m16n8k16.row.col.f32.f16.f16.f32 "
                        "{%0,%1,%2,%3}, {%4,%5,%6,%7}, {%8,%9}, {%0,%1,%2,%3};\n"
                        : "+f"(acc[mt][nt][0]), "+f"(acc[mt][nt][1]),
                          "+f"(acc[mt][nt][2]), "+f"(acc[mt][nt][3])
                        : "r"(afr[mt][0]), "r"(afr[mt][1]),
                          "r"(afr[mt][2]), "r"(afr[mt][3]),
                          "r"(bfr[nt][0]), "r"(bfr[nt][1]));
                }
            }
        }
        // no trailing barrier: next iteration's barrier (after wait) protects
        // stage reuse — writers of stage (t+2)&1 == t&1 only run after it.
    }

    // epilogue: bias + store (C fragment layout of m16n8)
#pragma unroll
    for (int mt = 0; mt < 2; mt++) {
        const int row0 = bm + wm * 32 + mt * 16 + q;
#pragma unroll
        for (int nt = 0; nt < 4; nt++) {
            const int col = bn + wn * 32 + nt * 8 + c * 2;
            const float b0 = g_b[col];
            const float b1 = g_b[col + 1];
            float2 v0 = make_float2(acc[mt][nt][0] + b0, acc[mt][nt][1] + b1);
            float2 v1 = make_float2(acc[mt][nt][2] + b0, acc[mt][nt][3] + b1);
            *reinterpret_cast<float2*>(OUT + (size_t)row0 * N_TOTAL + col) = v0;
            *reinterpret_cast<float2*>(OUT + (size_t)(row0 + 8) * N_TOTAL + col) = v1;
        }
    }
}

// ---------------------------------------------------------------------------
extern "C" void kernel_launch(void* const* d_in, const int* in_sizes, int n_in,
                              void* d_out, int out_size) {
    const float* x      = (const float*)d_in[0];
    const float* weight = (const float*)d_in[1];
    const float* bias   = (const float*)d_in[2];
    const float* scale  = (const float*)d_in[3];
    const int*   wq     = (const int*)  d_in[4];
    const float* wscale = (const float*)d_in[5];
    const int*   wzp    = (const int*)  d_in[6];
    const int*   bq     = (const int*)  d_in[7];
    const float* bscale = (const float*)d_in[8];
    const int*   bzp    = (const int*)  d_in[9];
    float* out = (float*)d_out;

    {
        const size_t nvec = (size_t)N_TOTAL * K_TOTAL / 4;
        compute_w_kernel<<<(int)((nvec + 255) / 256), 256>>>(weight, wq, scale, wscale, wzp);
    }
    {
        const size_t nvec = (size_t)M_TOTAL * K_TOTAL / 4;
        round_x_kernel<<<(int)((nvec + 255) / 256), 256>>>(x);
    }
    compute_b_kernel<<<(N_TOTAL + 255) / 256, 256>>>(bias, scale, bq, bscale, bzp);

    {
        int smem_bytes = STAGES * STAGE_B;   // 55296
        cudaFuncSetAttribute(gemm_fp16_kernel,
                             cudaFuncAttributeMaxDynamicSharedMemorySize, smem_bytes);
        dim3 grid(N_TOTAL / BN, M_TOTAL / BM);   // (64, 128)
        gemm_fp16_kernel<<<grid, 256, smem_bytes>>>(out);
    }
}

// round 15
// speedup vs baseline: 1.7630x; 1.1136x over previous
#include <cuda_runtime.h>
#include <cuda_fp16.h>
#include <cstdint>

#define M_TOTAL 16384
#define N_TOTAL 4096
#define K_TOTAL 4096
#define NSLOT   8

#define BM 128
#define BN 64
#define BK 64
#define STAGES 2
#define PADH 8
#define TSH (BK + PADH)        // 72 halves per row
#define ROWB (TSH * 2)         // 144 bytes per row
#define KT (K_TOTAL / BK)      // 64
#define ROWS_TOT (BM + BN)     // 192 rows per stage (A then B)
#define STAGE_B (ROWS_TOT * ROWB)  // 27648 bytes

// Scratch (allocation-free rule: __device__ globals)
__device__ __half g_W[(size_t)N_TOTAL * K_TOTAL];
__device__ __half g_X[(size_t)M_TOTAL * K_TOTAL];
__device__ float  g_b[N_TOTAL];

// ---------------------------------------------------------------------------
// Kernel 1: W = fp16(weight + sum_i (scale_i*wscale_i)*wq_i + (scale . wzp))
// ---------------------------------------------------------------------------
__global__ void compute_w_kernel(const float* __restrict__ weight,
                                 const int*   __restrict__ wq,
                                 const float* __restrict__ scale,
                                 const float* __restrict__ wscale,
                                 const int*   __restrict__ wzp) {
    const size_t nvec = (size_t)N_TOTAL * K_TOTAL / 4;
    size_t idx = (size_t)blockIdx.x * blockDim.x + threadIdx.x;
    if (idx >= nvec) return;

    float c[NSLOT];
    float z = 0.f;
#pragma unroll
    for (int i = 0; i < NSLOT; i++) {
        float s = scale[i];
        c[i] = s * wscale[i];
        z += s * (float)wzp[i];
    }
    float4 w = reinterpret_cast<const float4*>(weight)[idx];
    float ax = w.x + z, ay = w.y + z, az = w.z + z, aw = w.w + z;
#pragma unroll
    for (int i = 0; i < NSLOT; i++) {
        int4 q = reinterpret_cast<const int4*>(wq)[(size_t)i * nvec + idx];
        ax += c[i] * (float)q.x;
        ay += c[i] * (float)q.y;
        az += c[i] * (float)q.z;
        aw += c[i] * (float)q.w;
    }
    __half2 lo = __floats2half2_rn(ax, ay);
    __half2 hi = __floats2half2_rn(az, aw);
    reinterpret_cast<uint2*>(g_W)[idx] =
        make_uint2(*reinterpret_cast<uint32_t*>(&lo), *reinterpret_cast<uint32_t*>(&hi));
}

// ---------------------------------------------------------------------------
// Kernel 1b: X -> fp16
// ---------------------------------------------------------------------------
__global__ void round_x_kernel(const float* __restrict__ x) {
    const size_t nvec = (size_t)M_TOTAL * K_TOTAL / 4;
    size_t idx = (size_t)blockIdx.x * blockDim.x + threadIdx.x;
    if (idx >= nvec) return;
    float4 v = reinterpret_cast<const float4*>(x)[idx];
    __half2 lo = __floats2half2_rn(v.x, v.y);
    __half2 hi = __floats2half2_rn(v.z, v.w);
    reinterpret_cast<uint2*>(g_X)[idx] =
        make_uint2(*reinterpret_cast<uint32_t*>(&lo), *reinterpret_cast<uint32_t*>(&hi));
}

// ---------------------------------------------------------------------------
// Kernel 2: b = bias + sum_i scale_i*(bscale_i*bq_i + bzp_i)
// ---------------------------------------------------------------------------
__global__ void compute_b_kernel(const float* __restrict__ bias,
                                 const float* __restrict__ scale,
                                 const int*   __restrict__ bq,
                                 const float* __restrict__ bscale,
                                 const int*   __restrict__ bzp) {
    int j = blockIdx.x * blockDim.x + threadIdx.x;
    if (j >= N_TOTAL) return;
    float acc = bias[j];
#pragma unroll
    for (int i = 0; i < NSLOT; i++)
        acc += scale[i] * (bscale[i] * (float)bq[i * N_TOTAL + j] + (float)bzp[i]);
    g_b[j] = acc;
}

// ---------------------------------------------------------------------------
// Kernel 3: fp16 m16n8k16 GEMM, fp32 acc. CTA 128x64x64, 4 warps (2x2),
// warp tile 64x32, 128 threads, 2-stage cp.async, single barrier per k-tile.
// 4 CTAs/SM => 4 warps/SMSP in 4 independent barrier groups.
// ---------------------------------------------------------------------------
extern __shared__ __half smem_h[];

__global__ void __launch_bounds__(128, 4)
gemm_fp16_kernel(float* __restrict__ OUT) {
    const int tid  = threadIdx.x;
    const int warp = tid >> 5;
    const int lane = tid & 31;
    const int wm = warp >> 1;   // 0..1 : 64 rows
    const int wn = warp & 1;    // 0..1 : 32 cols
    const int bm = blockIdx.y * BM;
    const int bn = blockIdx.x * BN;

    const uint32_t S_u = (uint32_t)__cvta_generic_to_shared(smem_h);

    // producer: 192 rows x 8 chunks(16B) = 1536 chunks / 128 thr = 12 each.
    // chunk c = tid + 128*j -> row = (tid>>3) + 16*j, colchunk = tid&7.
    // smem rows 0..127 = A, 128..191 = B (B row = smem row - 128).
    const int prow0 = tid >> 3;          // 0..15
    const int pcc   = tid & 7;
    const __half* aP = g_X + (size_t)(bm + prow0) * K_TOTAL + pcc * 8;
    const __half* bP = g_W + (size_t)(bn + prow0) * K_TOTAL + pcc * 8;
    const uint32_t d0 = S_u + prow0 * ROWB + pcc * 16;

    auto issue_tile = [&](int t) {
        const uint32_t sb = (uint32_t)((t & 1) * STAGE_B);
        const int kofs = t * BK;
#pragma unroll
        for (int j = 0; j < 8; j++) {   // A rows prow0 + 16j
            asm volatile("cp.async.cg.shared.global [%0], [%1], 16;\n"
                         :: "r"(d0 + sb + j * 16 * ROWB),
                            "l"(aP + (size_t)j * 16 * K_TOTAL + kofs));
        }
#pragma unroll
        for (int j = 0; j < 4; j++) {   // B rows prow0 + 16j -> smem 128+
            asm volatile("cp.async.cg.shared.global [%0], [%1], 16;\n"
                         :: "r"(d0 + sb + (128 + j * 16) * ROWB),
                            "l"(bP + (size_t)j * 16 * K_TOTAL + kofs));
        }
    };

    float acc[4][4][4];
#pragma unroll
    for (int mt = 0; mt < 4; mt++)
#pragma unroll
        for (int nt = 0; nt < 4; nt++)
#pragma unroll
            for (int r = 0; r < 4; r++) acc[mt][nt][r] = 0.f;

    // ldmatrix per-lane base offsets (bytes within a stage)
    const uint32_t a_lm = (uint32_t)((wm * 64 + (lane & 15)) * ROWB + (lane >> 4) * 16);
    const uint32_t b_lm = (uint32_t)((128 + wn * 32 + ((lane >> 4) * 8 + (lane & 7))) * ROWB
                                     + ((lane >> 3) & 1) * 16);

    const int q = lane >> 2;
    const int c = lane & 3;

    issue_tile(0);
    asm volatile("cp.async.commit_group;\n");

    for (int t = 0; t < KT; t++) {
        asm volatile("cp.async.wait_group 0;\n");
        __syncthreads();

        if (t + 1 < KT) {
            issue_tile(t + 1);
            asm volatile("cp.async.commit_group;\n");
        }

        const uint32_t sb = (uint32_t)((t & 1) * STAGE_B);
        const uint32_t aS = S_u + sb + a_lm;
        const uint32_t bS = S_u + sb + b_lm;

#pragma unroll
        for (int ks = 0; ks < 4; ks++) {
            const uint32_t kb = (uint32_t)ks * 32;
            uint32_t afr[4][4];
#pragma unroll
            for (int mt = 0; mt < 4; mt++) {
                asm volatile(
                    "ldmatrix.sync.aligned.m8n8.x4.shared.b16 {%0,%1,%2,%3}, [%4];"
                    : "=r"(afr[mt][0]), "=r"(afr[mt][1]),
                      "=r"(afr[mt][2]), "=r"(afr[mt][3])
                    : "r"(aS + mt * 16 * ROWB + kb));
            }
            uint32_t bfr[4][2];
#pragma unroll
            for (int pr = 0; pr < 2; pr++) {
                asm volatile(
                    "ldmatrix.sync.aligned.m8n8.x4.shared.b16 {%0,%1,%2,%3}, [%4];"
                    : "=r"(bfr[2 * pr][0]), "=r"(bfr[2 * pr][1]),
                      "=r"(bfr[2 * pr + 1][0]), "=r"(bfr[2 * pr + 1][1])
                    : "r"(bS + pr * 16 * ROWB + kb));
            }
#pragma unroll
            for (int mt = 0; mt < 4; mt++) {
#pragma unroll
                for (int nt = 0; nt < 4; nt++) {
                    asm volatile(
                        "mma.sync.aligned.m16n8k16.row.col.f32.f16.f16.f32 "
                        "{%0,%1,%2,%3}, {%4,%5,%6,%7}, {%8,%9}, {%0,%1,%2,%3};\n"
                        : "+f"(acc[mt][nt][0]), "+f"(acc[mt][nt][1]),
                          "+f"(acc[mt][nt][2]), "+f"(acc[mt][nt][3])
                        : "r"(afr[mt][0]), "r"(afr[mt][1]),
                          "r"(afr[mt][2]), "r"(afr[mt][3]),
                          "r"(bfr[nt][0]), "r"(bfr[nt][1]));
                }
            }
        }
    }

    // epilogue: bias + store (C fragment layout of m16n8)
#pragma unroll
    for (int mt = 0; mt < 4; mt++) {
        const int row0 = bm + wm * 64 + mt * 16 + q;
#pragma unroll
        for (int nt = 0; nt < 4; nt++) {
            const int col = bn + wn * 32 + nt * 8 + c * 2;
            const float b0 = g_b[col];
            const float b1 = g_b[col + 1];
            float2 v0 = make_float2(acc[mt][nt][0] + b0, acc[mt][nt][1] + b1);
            float2 v1 = make_float2(acc[mt][nt][2] + b0, acc[mt][nt][3] + b1);
            *reinterpret_cast<float2*>(OUT + (size_t)row0 * N_TOTAL + col) = v0;
            *reinterpret_cast<float2*>(OUT + (size_t)(row0 + 8) * N_TOTAL + col) = v1;
        }
    }
}

// ---------------------------------------------------------------------------
extern "C" void kernel_launch(void* const* d_in, const int* in_sizes, int n_in,
                              void* d_out, int out_size) {
    const float* x      = (const float*)d_in[0];
    const float* weight = (const float*)d_in[1];
    const float* bias   = (const float*)d_in[2];
    const float* scale  = (const float*)d_in[3];
    const int*   wq     = (const int*)  d_in[4];
    const float* wscale = (const float*)d_in[5];
    const int*   wzp    = (const int*)  d_in[6];
    const int*   bq     = (const int*)  d_in[7];
    const float* bscale = (const float*)d_in[8];
    const int*   bzp    = (const int*)  d_in[9];
    float* out = (float*)d_out;

    {
        const size_t nvec = (size_t)N_TOTAL * K_TOTAL / 4;
        compute_w_kernel<<<(int)((nvec + 255) / 256), 256>>>(weight, wq, scale, wscale, wzp);
    }
    {
        const size_t nvec = (size_t)M_TOTAL * K_TOTAL / 4;
        round_x_kernel<<<(int)((nvec + 255) / 256), 256>>>(x);
    }
    compute_b_kernel<<<(N_TOTAL + 255) / 256, 256>>>(bias, scale, bq, bscale, bzp);

    {
        int smem_bytes = STAGES * STAGE_B;   // 55296
        cudaFuncSetAttribute(gemm_fp16_kernel,
                             cudaFuncAttributeMaxDynamicSharedMemorySize, smem_bytes);
        dim3 grid(N_TOTAL / BN, M_TOTAL / BM);   // (64, 128)
        gemm_fp16_kernel<<<grid, 128, smem_bytes>>>(out);
    }
}